// round 16
// baseline (speedup 1.0000x reference)
#include <cuda_runtime.h>

#define DIM      1024
#define NSTAGES  10
#define NTRIG    (NSTAGES * 512)          // 5120 float2 = 40 KB (permuted layout)

// smem: 40KB trig + 16KB exchange (4 warp-pairs x 1024-float private window).
// ZERO static smem so 4 CTAs/SM fit exactly: 4*(57344 + 1024 reserved) = 228KB.
#define SMEM_BYTES (NTRIG * 8 + 4096 * 4)   // 57344

// Two-tier tickets: tickets [0, SPLIT) process 2 rows; tickets [SPLIT,
// N_TICKETS) process 1 row (rowB aliases rowA; duplicate store is idempotent).
// SPLIT*2 + (N_TICKETS-SPLIT) = n_rows. Singles ~= number of pairs in flight
// (148 SMs * 4 CTAs * 4 pairs = 2368) so every pair's LAST batch is short.
#define N_ROWS    16384
#define N_SINGLE  2368
#define SPLIT     ((N_ROWS - N_SINGLE) / 2)   // 7008
#define N_TICKETS (SPLIT + N_SINGLE)          // 9376
#define BASE_S    (SPLIT * 2)                 // 14016

// Permuted, CONFLICT-FREE trig layout:
//   butterfly b of thread t6 (w*32+lane in warp-pair) at stage s lives at
//   float2 slot  s*512 + (b>>1)*128 + t6*2 + (b&1)
__device__ float2   g_trig[NTRIG];
__device__ unsigned g_ticket;

__device__ __forceinline__ int insert0(int b, int k)
{
    return ((b >> k) << (k + 1)) | (b & ((1 << k) - 1));
}

// Phase mappings (element index p, 10 bits):
//  P1: p = w*512 + c*128 + lane*4 + j          regs r=(c<<2)|j : bits {8,7,1,0}
//  P2: p = (lane&3) + 4r + 64*(lane>>2) + 512w regs = bits {5,4,3,2}
//  P3: p = lane + 32w + 64r                    regs = bits {9,8,7,6}
__global__ void build_trig_kernel(const float* __restrict__ angles)
{
    int idx = blockIdx.x * 256 + threadIdx.x;
    if (idx == 0) g_ticket = 0;           // reset dynamic scheduler each launch
    if (idx >= NTRIG) return;
    int s    = idx >> 9;
    int rem  = idx & 511;
    int kk   = rem >> 7;          // float4 group (0..3)
    int t6   = (rem >> 1) & 63;
    int e    = rem & 1;
    int b    = kk * 2 + e;        // butterfly index (0..7)
    int w    = t6 >> 5;
    int lane = t6 & 31;
    int k    = (s < 2) ? s : (s < 6 ? s - 2 : s - 6);
    int rL   = insert0(b, k);
    int p;
    if (s < 2)      p = w * 512 + (rL >> 2) * 128 + lane * 4 + (rL & 3);
    else if (s < 6) p = (lane & 3) + 4 * rL + 64 * (lane >> 2) + 512 * w;
    else            p = lane + 32 * w + 64 * rL;
    int ti = ((p >> (s + 1)) << s) | (p & ((1 << s) - 1));
    float sv, cv;
    sincosf(angles[s * 512 + ti], &sv, &cv);
    g_trig[idx] = make_float2(cv, sv);
}

__device__ __forceinline__ void rot(float& L, float& R, float c, float s)
{
    float l = L;
    L = fmaf(c, l,  s * R);
    R = fmaf(c, R, -s * l);
}

// One register-local stage on TWO rows sharing the same trig.
template<int K>
__device__ __forceinline__ void do_stage(float* vA, float* vB, const float4* tb4)
{
    float4 q0 = tb4[0], q1 = tb4[64], q2 = tb4[128], q3 = tb4[192];
    const float cs[8] = {q0.x,q0.z,q1.x,q1.z,q2.x,q2.z,q3.x,q3.z};
    const float sn[8] = {q0.y,q0.w,q1.y,q1.w,q2.y,q2.w,q3.y,q3.w};
    #pragma unroll
    for (int b = 0; b < 8; b++) {
        const int rL = ((b >> K) << (K + 1)) | (b & ((1 << K) - 1));
        const int rR = rL | (1 << K);
        rot(vA[rL], vA[rR], cs[b], sn[b]);
        rot(vB[rL], vB[rR], cs[b], sn[b]);
    }
}

// E1: intra-warp remap P1 -> P2 through a warp-private 512-float smem segment.
// XOR swizzle addr = q ^ (((q>>6)&7)<<2): conflict-free writes AND reads.
__device__ __forceinline__ void exch1(float* v, float* seg, int lane)
{
    #pragma unroll
    for (int c = 0; c < 4; c++) {
        int q0 = c * 128 + lane * 4;
        int a  = q0 ^ (((q0 >> 6) & 7) << 2);
        *(float4*)(seg + a) = make_float4(v[4*c], v[4*c+1], v[4*c+2], v[4*c+3]);
    }
    __syncwarp();
    const int A   = (lane & 3) + 64 * (lane >> 2);
    const int swz = ((lane >> 2) & 7) << 2;
    #pragma unroll
    for (int r = 0; r < 16; r++)
        v[r] = seg[(A + 4 * r) ^ swz];
    __syncwarp();
}

#define PAIR_BAR() asm volatile("bar.sync %0, 64;" :: "r"(pr + 1) : "memory")

__global__ __launch_bounds__(256, 4) void butterfly_kernel(
    const float* __restrict__ x,
    float* __restrict__ out)
{
    extern __shared__ float smem_raw[];
    float2* s_trig = (float2*)smem_raw;            // 5120 float2
    float*  s_xch  = smem_raw + 2 * NTRIG;         // 4096 floats

    const int tid  = threadIdx.x;
    const int lane = tid & 31;
    const int ww   = tid >> 5;
    const int w    = ww & 1;
    const int pr   = ww >> 1;
    const int t6   = w * 32 + lane;
    const bool leader = ((tid & 63) == 0);         // w0 lane0 of each pair

    // One-time trig table copy (amortized over the dynamic loop).
    {
        const float4* gt = (const float4*)g_trig;
        float4*       st = (float4*)s_trig;
        #pragma unroll
        for (int i = 0; i < NTRIG / 2 / 256; i++)
            st[i * 256 + tid] = __ldcs(gt + i * 256 + tid);
    }

    const float4* tb4 = (const float4*)s_trig + t6;   // + s*256 per stage

    // Pair-private 1024-float window. Each warp's E1 segment and its E2 write
    // half are the same [w*512, w*512+512) slice; only E2 READS cross halves.
    float* pwin = s_xch + pr * 1024;
    float* seg  = pwin + w * 512;

    // Pair ticket slot = pwin[0]. Outside the publish/reuse barriers it is
    // touched ONLY by the pair leader itself (all index-0 accesses require
    // lane==0 && w==0 && r==0).
    volatile int* tick = (volatile int*)pwin;

    if (leader)
        tick[0] = (int)atomicAdd(&g_ticket, 1u);   // first ticket
    __syncthreads();                                // covers trig copy + publish

    const int B2    = (lane & 3) + 64 * (lane >> 2) + 512 * w;
    const int swz2  = ((lane >> 2) & 7) << 2;
    const int rbase = lane + 32 * w;

    for (;;) {
        const int t = tick[0];            // ordered after previous publish bar
        PAIR_BAR();                       // both warps read -> slot/window reusable
        if (t >= N_TICKETS) break;        // pair-uniform exit

        // Two-tier ticket -> rows. Doubles: rows (2t, 2t+1). Singles: one row,
        // rowB aliases rowA (same loads, idempotent duplicate stores).
        const bool dbl  = (t < SPLIT);
        const int  rowA = dbl ? (t * 2) : (BASE_S + (t - SPLIT));
        const int  off4 = dbl ? 256 : 0;          // rowB float4 offset
        const int  offs = dbl ? DIM : 0;          // rowB float offset (stores)

        float vA[16], vB[16];

        // -------- Phase 1: coalesced streaming loads + stages 0,1 --------
        const float4* xr = (const float4*)(x + (size_t)rowA * DIM + w * 512);
        #pragma unroll
        for (int c = 0; c < 4; c++) {
            float4 a = __ldcs(xr + c * 32 + lane);
            vA[c*4+0]=a.x; vA[c*4+1]=a.y; vA[c*4+2]=a.z; vA[c*4+3]=a.w;
            float4 b = __ldcs(xr + c * 32 + lane + off4);
            vB[c*4+0]=b.x; vB[c*4+1]=b.y; vB[c*4+2]=b.z; vB[c*4+3]=b.w;
        }

        do_stage<0>(vA, vB, tb4 + 0 * 256);
        do_stage<1>(vA, vB, tb4 + 1 * 256);

        // -------- E1: per-warp remap (syncwarp only, warp-private) --------
        exch1(vA, seg, lane);
        exch1(vB, seg, lane);

        // -------- Phase 2: stages 2..5 --------
        do_stage<0>(vA, vB, tb4 + 2 * 256);
        do_stage<1>(vA, vB, tb4 + 3 * 256);
        do_stage<2>(vA, vB, tb4 + 4 * 256);
        do_stage<3>(vA, vB, tb4 + 5 * 256);

        // -------- E2: warp-pair remap P2 -> P3 (pair-local barriers) ------
        // Writes land in own half (no bar needed after E1); reads cross.
        #pragma unroll
        for (int r = 0; r < 16; r++)
            seg[((B2 + 4 * r) ^ swz2) - w * 512] = vA[r];  // == pwin[(B2+4r)^swz2]
        PAIR_BAR();
        #pragma unroll
        for (int r = 0; r < 16; r++)
            vA[r] = pwin[(rbase + 64 * r) ^ ((r & 7) << 2)];
        PAIR_BAR();                       // reads done before overwrite with B
        #pragma unroll
        for (int r = 0; r < 16; r++)
            seg[((B2 + 4 * r) ^ swz2) - w * 512] = vB[r];
        PAIR_BAR();
        #pragma unroll
        for (int r = 0; r < 16; r++)
            vB[r] = pwin[(rbase + 64 * r) ^ ((r & 7) << 2)];

        // -------- leader: prefetch next ticket + its rows into L2 ---------
        // Leader's last slot-0 access (its vB read at r=0) is complete above
        // in program order; no other thread touches slot 0 until after the
        // publish PAIR_BAR below.
        if (leader) {
            int nb = (int)atomicAdd(&g_ticket, 1u);
            tick[0] = nb;
            if (nb < N_TICKETS) {
                const bool ndbl = (nb < SPLIT);
                const int  nrow = ndbl ? (nb * 2) : (BASE_S + (nb - SPLIT));
                const float* pf = x + (size_t)nrow * DIM;
                int bytes = ndbl ? (2 * DIM * 4) : (DIM * 4);
                asm volatile("cp.async.bulk.prefetch.L2.global [%0], %1;"
                             :: "l"(pf), "r"(bytes) : "memory");
            }
        }

        // -------- Phase 3: stages 6..9 --------
        do_stage<0>(vA, vB, tb4 + 6 * 256);
        do_stage<1>(vA, vB, tb4 + 7 * 256);
        do_stage<2>(vA, vB, tb4 + 8 * 256);
        do_stage<3>(vA, vB, tb4 + 9 * 256);

        // -------- Store (P3: coalesced 32-bit streaming stores) -----------
        // Singles: offs==0 -> vB stores hit the same addresses with the same
        // values (vB computed from identical inputs) -> benign.
        float* o = out + (size_t)rowA * DIM + rbase;
        #pragma unroll
        for (int r = 0; r < 16; r++) {
            __stcs(o + 64 * r,        vA[r]);
            __stcs(o + 64 * r + offs, vB[r]);
        }

        PAIR_BAR();                       // publish prefetched ticket
    }
}

extern "C" void kernel_launch(void* const* d_in, const int* in_sizes, int n_in,
                              void* d_out, int out_size)
{
    const float* x      = (const float*)d_in[0];
    const float* angles = (const float*)d_in[1];
    float*       out    = (float*)d_out;

    build_trig_kernel<<<(NTRIG + 255) / 256, 256>>>(angles);

    cudaFuncSetAttribute(butterfly_kernel,
                         cudaFuncAttributeMaxDynamicSharedMemorySize, SMEM_BYTES);

    butterfly_kernel<<<592, 256, SMEM_BYTES>>>(x, out);
}

// round 17
// speedup vs baseline: 1.1763x; 1.1763x over previous
#include <cuda_runtime.h>

#define DIM      1024
#define NSTAGES  10
#define NTRIG    (NSTAGES * 512)          // 5120 float2 = 40 KB (permuted layout)

// smem: 40KB trig + 32KB exchange (4 warp-pairs x 2048-float private window).
// 2 CTAs/SM (register-limited: 256 thr x 128 regs = half the RF), so the smem
// budget is ample: 2*(73728+1024) = 149.5KB <= 228KB.
#define SMEM_BYTES (NTRIG * 8 + 8192 * 4)   // 73728

// Permuted, CONFLICT-FREE trig layout:
//   butterfly b of thread t6 (w*32+lane in warp-pair) at stage s lives at
//   float2 slot  s*512 + (b>>1)*128 + t6*2 + (b&1)
__device__ float2   g_trig[NTRIG];
__device__ unsigned g_ticket;

__device__ __forceinline__ int insert0(int b, int k)
{
    return ((b >> k) << (k + 1)) | (b & ((1 << k) - 1));
}

// Phase mappings (element index p, 10 bits):
//  P1: p = w*512 + c*128 + lane*4 + j          regs r=(c<<2)|j : bits {8,7,1,0}
//  P2: p = (lane&3) + 4r + 64*(lane>>2) + 512w regs = bits {5,4,3,2}
//  P3: p = lane + 32w + 64r                    regs = bits {9,8,7,6}
__global__ void build_trig_kernel(const float* __restrict__ angles)
{
    int idx = blockIdx.x * 256 + threadIdx.x;
    if (idx == 0) g_ticket = 0;           // reset dynamic scheduler each launch
    if (idx >= NTRIG) return;
    int s    = idx >> 9;
    int rem  = idx & 511;
    int kk   = rem >> 7;          // float4 group (0..3)
    int t6   = (rem >> 1) & 63;
    int e    = rem & 1;
    int b    = kk * 2 + e;        // butterfly index (0..7)
    int w    = t6 >> 5;
    int lane = t6 & 31;
    int k    = (s < 2) ? s : (s < 6 ? s - 2 : s - 6);
    int rL   = insert0(b, k);
    int p;
    if (s < 2)      p = w * 512 + (rL >> 2) * 128 + lane * 4 + (rL & 3);
    else if (s < 6) p = (lane & 3) + 4 * rL + 64 * (lane >> 2) + 512 * w;
    else            p = lane + 32 * w + 64 * rL;
    int ti = ((p >> (s + 1)) << s) | (p & ((1 << s) - 1));
    float sv, cv;
    sincosf(angles[s * 512 + ti], &sv, &cv);
    g_trig[idx] = make_float2(cv, sv);
}

__device__ __forceinline__ void rot(float& L, float& R, float c, float s)
{
    float l = L;
    L = fmaf(c, l,  s * R);
    R = fmaf(c, R, -s * l);
}

// One register-local stage on FOUR rows sharing the same trig.
// Trig loaded one float4 at a time to cap live registers.
template<int K>
__device__ __forceinline__ void do_stage4(float* vA, float* vB, float* vC,
                                          float* vD, const float4* tb4)
{
    #pragma unroll
    for (int g = 0; g < 4; g++) {
        float4 q = tb4[g * 64];
        #pragma unroll
        for (int e = 0; e < 2; e++) {
            const int b  = g * 2 + e;
            const int rL = ((b >> K) << (K + 1)) | (b & ((1 << K) - 1));
            const int rR = rL | (1 << K);
            const float c = e ? q.z : q.x;
            const float s = e ? q.w : q.y;
            rot(vA[rL], vA[rR], c, s);
            rot(vB[rL], vB[rR], c, s);
            rot(vC[rL], vC[rR], c, s);
            rot(vD[rL], vD[rR], c, s);
        }
    }
}

// E1: intra-warp remap P1 -> P2 through a warp-private 512-float smem segment.
// XOR swizzle addr = q ^ (((q>>6)&7)<<2): conflict-free writes AND reads.
__device__ __forceinline__ void exch1(float* v, float* seg, int lane)
{
    #pragma unroll
    for (int c = 0; c < 4; c++) {
        int q0 = c * 128 + lane * 4;
        int a  = q0 ^ (((q0 >> 6) & 7) << 2);
        *(float4*)(seg + a) = make_float4(v[4*c], v[4*c+1], v[4*c+2], v[4*c+3]);
    }
    __syncwarp();
    const int A   = (lane & 3) + 64 * (lane >> 2);
    const int swz = ((lane >> 2) & 7) << 2;
    #pragma unroll
    for (int r = 0; r < 16; r++)
        v[r] = seg[(A + 4 * r) ^ swz];
    __syncwarp();
}

#define PAIR_BAR() asm volatile("bar.sync %0, 64;" :: "r"(pr + 1) : "memory")

__global__ __launch_bounds__(256, 2) void butterfly_kernel(
    const float* __restrict__ x,
    float* __restrict__ out,
    int n_tickets)                       // n_rows / 4
{
    extern __shared__ float smem_raw[];
    float2* s_trig = (float2*)smem_raw;            // 5120 float2
    float*  s_xch  = smem_raw + 2 * NTRIG;         // 8192 floats

    const int tid  = threadIdx.x;
    const int lane = tid & 31;
    const int ww   = tid >> 5;
    const int w    = ww & 1;
    const int pr   = ww >> 1;
    const int t6   = w * 32 + lane;
    const bool leader = ((tid & 63) == 0);         // w0 lane0 of each pair

    // One-time trig table copy (amortized over the dynamic loop).
    {
        const float4* gt = (const float4*)g_trig;
        float4*       st = (float4*)s_trig;
        #pragma unroll
        for (int i = 0; i < NTRIG / 2 / 256; i++)
            st[i * 256 + tid] = __ldcs(gt + i * 256 + tid);
    }

    const float4* tb4 = (const float4*)s_trig + t6;   // + s*256 per stage

    // Pair-private 2048-float window: win0=[0,1024), win1=[1024,2048).
    // E1 segment = win0 + w*512 (warp-disjoint). E2 transposes rows in
    // PAIRS: first row of a pass -> win0, second -> win1.
    float* pwin = s_xch + pr * 2048;
    float* win1 = pwin + 1024;
    float* seg  = pwin + w * 512;

    // Pair ticket slot = pwin[0]. Outside the publish/reuse barriers it is
    // touched ONLY by the pair leader itself: all index-0 accesses (E1 w/r,
    // E2 win0 write (B2+4r)^swz2==0 and read (rbase+64r)^swz==0) require
    // lane==0 && w==0 && r==0. win1 never maps to offset 0.
    volatile int* tick = (volatile int*)pwin;

    if (leader)
        tick[0] = (int)atomicAdd(&g_ticket, 1u);   // first ticket
    __syncthreads();                                // covers trig copy + publish

    const int B2    = (lane & 3) + 64 * (lane >> 2) + 512 * w;
    const int swz2  = ((lane >> 2) & 7) << 2;
    const int rbase = lane + 32 * w;

    for (;;) {
        const int t = tick[0];            // ordered after previous publish bar
        PAIR_BAR();                       // both warps read -> slot/window reusable
        if (t >= n_tickets) break;        // pair-uniform exit

        const int rowA = t * 4;           // rows rowA .. rowA+3

        float vA[16], vB[16], vC[16], vD[16];

        // -------- Phase 1: coalesced streaming loads + stages 0,1 --------
        const float4* xr = (const float4*)(x + (size_t)rowA * DIM + w * 512);
        #pragma unroll
        for (int c = 0; c < 4; c++) {
            float4 a = __ldcs(xr + c * 32 + lane);
            vA[c*4+0]=a.x; vA[c*4+1]=a.y; vA[c*4+2]=a.z; vA[c*4+3]=a.w;
            float4 b = __ldcs(xr + c * 32 + lane + 256);
            vB[c*4+0]=b.x; vB[c*4+1]=b.y; vB[c*4+2]=b.z; vB[c*4+3]=b.w;
            float4 cc = __ldcs(xr + c * 32 + lane + 512);
            vC[c*4+0]=cc.x; vC[c*4+1]=cc.y; vC[c*4+2]=cc.z; vC[c*4+3]=cc.w;
            float4 d = __ldcs(xr + c * 32 + lane + 768);
            vD[c*4+0]=d.x; vD[c*4+1]=d.y; vD[c*4+2]=d.z; vD[c*4+3]=d.w;
        }

        do_stage4<0>(vA, vB, vC, vD, tb4 + 0 * 256);
        do_stage4<1>(vA, vB, vC, vD, tb4 + 1 * 256);

        // -------- E1: per-warp remap (syncwarp only, warp-private) --------
        exch1(vA, seg, lane);
        exch1(vB, seg, lane);
        exch1(vC, seg, lane);
        exch1(vD, seg, lane);

        // -------- Phase 2: stages 2..5 --------
        do_stage4<0>(vA, vB, vC, vD, tb4 + 2 * 256);
        do_stage4<1>(vA, vB, vC, vD, tb4 + 3 * 256);
        do_stage4<2>(vA, vB, vC, vD, tb4 + 4 * 256);
        do_stage4<3>(vA, vB, vC, vD, tb4 + 5 * 256);

        // -------- E2: warp-pair remap P2 -> P3, two rows per pass ---------
        // Writes land in each warp's own half of each window (no bar after
        // E1 needed); reads cross halves -> pair barriers.
        #pragma unroll
        for (int r = 0; r < 16; r++) {
            const int a = (B2 + 4 * r) ^ swz2;
            pwin[a] = vA[r];
            win1[a] = vB[r];
        }
        PAIR_BAR();
        #pragma unroll
        for (int r = 0; r < 16; r++) {
            const int a = (rbase + 64 * r) ^ ((r & 7) << 2);
            vA[r] = pwin[a];
            vB[r] = win1[a];
        }
        PAIR_BAR();                       // reads done before overwrite
        #pragma unroll
        for (int r = 0; r < 16; r++) {
            const int a = (B2 + 4 * r) ^ swz2;
            pwin[a] = vC[r];
            win1[a] = vD[r];
        }
        PAIR_BAR();
        #pragma unroll
        for (int r = 0; r < 16; r++) {
            const int a = (rbase + 64 * r) ^ ((r & 7) << 2);
            vC[r] = pwin[a];
            vD[r] = win1[a];
        }

        // -------- leader: prefetch next ticket + its 4 rows into L2 -------
        // Leader's last slot-0 access (vC read at r=0) is complete above in
        // program order; no other thread touches slot 0 until after the
        // publish PAIR_BAR below.
        if (leader) {
            int nb = (int)atomicAdd(&g_ticket, 1u);
            tick[0] = nb;
            if (nb < n_tickets) {
                const float* pf = x + (size_t)nb * 4 * DIM;
                asm volatile("cp.async.bulk.prefetch.L2.global [%0], %1;"
                             :: "l"(pf), "r"(4 * DIM * 4) : "memory");
            }
        }

        // -------- Phase 3: stages 6..9 --------
        do_stage4<0>(vA, vB, vC, vD, tb4 + 6 * 256);
        do_stage4<1>(vA, vB, vC, vD, tb4 + 7 * 256);
        do_stage4<2>(vA, vB, vC, vD, tb4 + 8 * 256);
        do_stage4<3>(vA, vB, vC, vD, tb4 + 9 * 256);

        // -------- Store (P3: coalesced 32-bit streaming stores) -----------
        float* o = out + (size_t)rowA * DIM + rbase;
        #pragma unroll
        for (int r = 0; r < 16; r++) {
            __stcs(o + 64 * r,           vA[r]);
            __stcs(o + 64 * r + DIM,     vB[r]);
            __stcs(o + 64 * r + 2 * DIM, vC[r]);
            __stcs(o + 64 * r + 3 * DIM, vD[r]);
        }

        PAIR_BAR();                       // publish prefetched ticket
    }
}

extern "C" void kernel_launch(void* const* d_in, const int* in_sizes, int n_in,
                              void* d_out, int out_size)
{
    const float* x      = (const float*)d_in[0];
    const float* angles = (const float*)d_in[1];
    float*       out    = (float*)d_out;

    const int n_rows    = in_sizes[0] / DIM;   // 16384
    const int n_tickets = n_rows / 4;          // 4096 (4 rows per pair ticket)

    build_trig_kernel<<<(NTRIG + 255) / 256, 256>>>(angles);

    cudaFuncSetAttribute(butterfly_kernel,
                         cudaFuncAttributeMaxDynamicSharedMemorySize, SMEM_BYTES);

    butterfly_kernel<<<296, 256, SMEM_BYTES>>>(x, out, n_tickets);
}